// round 16
// baseline (speedup 1.0000x reference)
#include <cuda_runtime.h>
#include <math.h>

#define NB 32
#define CCH 384
#define HWP 3136
#define MM 8
#define DD 768
#define EE 768   // 2*C

typedef unsigned long long u64;

// ---------------- packed f32x2 helpers ----------------
__device__ __forceinline__ void fma2(u64& acc, u64 a, u64 b) {
    asm("fma.rn.f32x2 %0, %1, %2, %0;" : "+l"(acc) : "l"(a), "l"(b));
}
__device__ __forceinline__ u64 mul2(u64 a, u64 b) {
    u64 d; asm("mul.rn.f32x2 %0, %1, %2;" : "=l"(d) : "l"(a), "l"(b)); return d;
}
__device__ __forceinline__ u64 add2(u64 a, u64 b) {
    u64 d; asm("add.rn.f32x2 %0, %1, %2;" : "=l"(d) : "l"(a), "l"(b)); return d;
}
__device__ __forceinline__ u64 dup2(float v) {
    u64 d; asm("mov.b64 %0, {%1, %1};" : "=l"(d) : "f"(v)); return d;
}
__device__ __forceinline__ u64 pack2(float lo, float hi) {
    u64 d; asm("mov.b64 %0, {%1, %2};" : "=l"(d) : "f"(lo), "f"(hi)); return d;
}
__device__ __forceinline__ void unpack2(u64 v, float& lo, float& hi) {
    asm("mov.b64 {%0, %1}, %2;" : "=f"(lo), "=f"(hi) : "l"(v));
}
__device__ __forceinline__ float hadd2(u64 v) {
    float lo, hi; unpack2(v, lo, hi); return lo + hi;
}

// ---------------- device scratch (no allocations allowed) ----------------
__device__ __align__(16) float g_Kt[NB * CCH * MM]; // [n][c][k]
__device__ __align__(16) float g_Vt[NB * CCH * MM]; // [n][c][k]

// ---------------- kernel 1: kv = clip(gf @ W^T + b, 0, 6) ----------------
// NT GEMM (no transpose), packed f32x2 FMA, software-pipelined chunk loads.
// KB_E=32 -> 384 CTAs for parallelism.
#define KB_E 32
#define KB_R 16
#define KB_D 64

__device__ __forceinline__ void kv_store(int row, int e, float v) {
    int n = row >> 3;
    int m = row & 7;
    if (e < CCH) g_Kt[((size_t)n * CCH + e) * MM + m] = v;
    else         g_Vt[((size_t)n * CCH + (e - CCH)) * MM + m] = v;
}

__global__ __launch_bounds__(128) void k_kv(const float* __restrict__ gf,
                                            const float* __restrict__ W,
                                            const float* __restrict__ bias) {
    __shared__ float Wc[KB_E][68];   // 8704 B
    __shared__ float Gc[KB_R][68];   // 4352 B

    int t    = threadIdx.x;
    int lane = t & 31;
    int warp = t >> 5;
    int eb0  = blockIdx.x * KB_E;
    int rb0  = blockIdx.y * KB_R;
    int ei   = lane & 15;            // e = eb0 + ei + 16q
    int rg   = lane >> 4;            // 0..1
    int r0   = warp * 4 + rg * 2;    // local row base (2 rows)

    int wrow = t >> 4, wf4 = t & 15; // staging coords

    u64 acc[2][2];
#pragma unroll
    for (int q = 0; q < 2; q++) { acc[q][0] = 0ull; acc[q][1] = 0ull; }

    // prologue: fetch chunk 0 into registers
    float4 wreg[4], greg[2];
#pragma unroll
    for (int q = 0; q < 4; q++)
        wreg[q] = *(const float4*)(W + (size_t)(eb0 + wrow + q * 8) * DD + wf4 * 4);
#pragma unroll
    for (int q = 0; q < 2; q++)
        greg[q] = *(const float4*)(gf + (size_t)(rb0 + wrow + q * 8) * DD + wf4 * 4);

    for (int kc = 0; kc < DD; kc += KB_D) {
        __syncthreads();
#pragma unroll
        for (int q = 0; q < 4; q++)
            *(float4*)(&Wc[wrow + q * 8][wf4 * 4]) = wreg[q];
#pragma unroll
        for (int q = 0; q < 2; q++)
            *(float4*)(&Gc[wrow + q * 8][wf4 * 4]) = greg[q];
        __syncthreads();
        if (kc + KB_D < DD) {
#pragma unroll
            for (int q = 0; q < 4; q++)
                wreg[q] = *(const float4*)(W + (size_t)(eb0 + wrow + q * 8) * DD + kc + KB_D + wf4 * 4);
#pragma unroll
            for (int q = 0; q < 2; q++)
                greg[q] = *(const float4*)(gf + (size_t)(rb0 + wrow + q * 8) * DD + kc + KB_D + wf4 * 4);
        }
#pragma unroll
        for (int s = 0; s < 16; s++) {
            ulonglong2 g0 = *(const ulonglong2*)(&Gc[r0][s * 4]);
            ulonglong2 g1 = *(const ulonglong2*)(&Gc[r0 + 1][s * 4]);
#pragma unroll
            for (int q = 0; q < 2; q++) {
                ulonglong2 w = *(const ulonglong2*)(&Wc[ei + 16 * q][s * 4]);
                fma2(acc[q][0], g0.x, w.x);
                fma2(acc[q][0], g0.y, w.y);
                fma2(acc[q][1], g1.x, w.x);
                fma2(acc[q][1], g1.y, w.y);
            }
        }
    }

#pragma unroll
    for (int q = 0; q < 2; q++) {
        int e = eb0 + ei + 16 * q;
        float bv = bias[e];
        float v0 = fminf(fmaxf(hadd2(acc[q][0]) + bv, 0.f), 6.f);
        float v1 = fminf(fmaxf(hadd2(acc[q][1]) + bv, 0.f), 6.f);
        kv_store(rb0 + r0,     e, v0);
        kv_store(rb0 + r0 + 1, e, v1);
    }
}

// ---------------- kernel 2: fused attention + residual ----------------
// v5: 8 pixels/thread, 8 parts x 48 ch, packed f32x2 FMA, pass-2 L2 re-read.
// Lane map: part r = lane>>2, pixel octet li = lane&3 (p = ... + li*8).
// Warp = 32 px, CTA (64 thr) = 64 px, grid (49, 32) exact.
// K/V smem skew: f4 idx(c, half) = 2c + (c/48) + half ; part base = 97r
// -> 8 parts' broadcast LDS.128 on the 8 disjoint 4-bank groups.
__global__ __launch_bounds__(64, 8) void k_attn(const float* __restrict__ x,
                                                float* __restrict__ out) {
    __shared__ float4 Ks4[776];
    __shared__ float4 Vs4[776];

    int tid  = threadIdx.x;
    int n    = blockIdx.y;
    int lane = tid & 31;
    int warp = tid >> 5;
    int r    = lane >> 2;                        // 0..7
    int li   = lane & 3;
    int p    = blockIdx.x * 64 + warp * 32 + li * 8;

    const float4* Kt4 = (const float4*)g_Kt + (size_t)n * (CCH * MM / 4);
    const float4* Vt4 = (const float4*)g_Vt + (size_t)n * (CCH * MM / 4);
#pragma unroll
    for (int i = tid; i < 768; i += 64) {
        int c = i >> 1, half = i & 1;
        int dst = 2 * c + (c / 48) + half;
        Ks4[dst] = Kt4[i];
        Vs4[dst] = Vt4[i];
    }
    __syncthreads();

    const ulonglong2* Ks2 = (const ulonglong2*)Ks4;
    const ulonglong2* Vs2 = (const ulonglong2*)Vs4;
    const float* xp = x + ((size_t)n * CCH + r * 48) * HWP + p;
    int base = 97 * r;

    // ---- pass 1: packed partial scores, chunks of 4 channels ----
    u64 sp[8][4];
#pragma unroll
    for (int e = 0; e < 8; e++)
#pragma unroll
        for (int q = 0; q < 4; q++) sp[e][q] = 0ull;

#pragma unroll
    for (int ch = 0; ch < 12; ch++) {
        float4 xa[4], xb[4];
#pragma unroll
        for (int u = 0; u < 4; u++) {
            const float* px_ = xp + (size_t)(ch * 4 + u) * HWP;
            xa[u] = *(const float4*)px_;
            xb[u] = *(const float4*)(px_ + 4);
        }
        asm volatile("" ::: "memory");
#pragma unroll
        for (int u = 0; u < 4; u++) {
            int j = ch * 4 + u;
            ulonglong2 kA = Ks2[base + 2 * j];
            ulonglong2 kB = Ks2[base + 2 * j + 1];
            float xv[8] = {xa[u].x, xa[u].y, xa[u].z, xa[u].w,
                           xb[u].x, xb[u].y, xb[u].z, xb[u].w};
#pragma unroll
            for (int e = 0; e < 8; e++) {
                u64 d = dup2(xv[e]);
                fma2(sp[e][0], d, kA.x);
                fma2(sp[e][1], d, kA.y);
                fma2(sp[e][2], d, kB.x);
                fma2(sp[e][3], d, kB.y);
            }
        }
    }

    // ---- reduce across the 8 parts (xor 4, 8, 16), packed adds ----
#pragma unroll
    for (int e = 0; e < 8; e++)
#pragma unroll
        for (int q = 0; q < 4; q++) {
            u64 v = sp[e][q];
            v = add2(v, __shfl_xor_sync(0xffffffffu, v, 4));
            v = add2(v, __shfl_xor_sync(0xffffffffu, v, 8));
            v = add2(v, __shfl_xor_sync(0xffffffffu, v, 16));
            sp[e][q] = v;
        }

    // ---- softmax over 8 heads per pixel; repack attn as head-pairs ----
    u64 ap[8][4];
#pragma unroll
    for (int e = 0; e < 8; e++) {
        float h0,h1,h2,h3,h4,h5,h6,h7;
        unpack2(sp[e][0], h0, h1);
        unpack2(sp[e][1], h2, h3);
        unpack2(sp[e][2], h4, h5);
        unpack2(sp[e][3], h6, h7);
        float mx = fmaxf(fmaxf(fmaxf(h0, h1), fmaxf(h2, h3)),
                         fmaxf(fmaxf(h4, h5), fmaxf(h6, h7)));
        float e0 = __expf(h0 - mx), e1 = __expf(h1 - mx);
        float e2 = __expf(h2 - mx), e3 = __expf(h3 - mx);
        float e4 = __expf(h4 - mx), e5 = __expf(h5 - mx);
        float e6 = __expf(h6 - mx), e7 = __expf(h7 - mx);
        float inv = __fdividef(1.f, e0+e1+e2+e3+e4+e5+e6+e7);
        ap[e][0] = pack2(e0 * inv, e1 * inv);
        ap[e][1] = pack2(e2 * inv, e3 * inv);
        ap[e][2] = pack2(e4 * inv, e5 * inv);
        ap[e][3] = pack2(e6 * inv, e7 * inv);
    }

    // ---- pass 2: out = attn.V + x (x re-read; L2-resident), chunks of 2 ----
    float* op = out + ((size_t)n * CCH + r * 48) * HWP + p;
#pragma unroll
    for (int ch = 0; ch < 24; ch++) {
        float4 xa[2], xb[2];
#pragma unroll
        for (int u = 0; u < 2; u++) {
            const float* px_ = xp + (size_t)(ch * 2 + u) * HWP;
            xa[u] = *(const float4*)px_;
            xb[u] = *(const float4*)(px_ + 4);
        }
        asm volatile("" ::: "memory");
#pragma unroll
        for (int u = 0; u < 2; u++) {
            int j = ch * 2 + u;
            ulonglong2 vA = Vs2[base + 2 * j];
            ulonglong2 vB = Vs2[base + 2 * j + 1];
            float xv[8] = {xa[u].x, xa[u].y, xa[u].z, xa[u].w,
                           xb[u].x, xb[u].y, xb[u].z, xb[u].w};
            float o[8];
#pragma unroll
            for (int e = 0; e < 8; e++) {
                u64 acc = mul2(ap[e][0], vA.x);
                fma2(acc, ap[e][1], vA.y);
                fma2(acc, ap[e][2], vB.x);
                fma2(acc, ap[e][3], vB.y);
                o[e] = hadd2(acc) + xv[e];
            }
            __stcs((float4*)(op + (size_t)j * HWP),
                   make_float4(o[0], o[1], o[2], o[3]));
            __stcs((float4*)(op + (size_t)j * HWP + 4),
                   make_float4(o[4], o[5], o[6], o[7]));
        }
    }
}

// ---------------- launch ----------------
extern "C" void kernel_launch(void* const* d_in, const int* in_sizes, int n_in,
                              void* d_out, int out_size) {
    const float* x  = (const float*)d_in[0];
    const float* gf = (const float*)d_in[1];
    const float* W  = (const float*)d_in[2];
    const float* b  = (const float*)d_in[3];
    float* out = (float*)d_out;

    k_kv<<<dim3(EE / KB_E, 256 / KB_R), 128>>>(gf, W, b);
    k_attn<<<dim3(HWP / 64, NB), 64>>>(x, out);
}

// round 17
// speedup vs baseline: 2.8543x; 2.8543x over previous
#include <cuda_runtime.h>
#include <math.h>

#define NB 32
#define CCH 384
#define HWP 3136
#define MM 8
#define DD 768
#define EE 768   // 2*C

typedef unsigned long long u64;

// ---------------- packed f32x2 helpers ----------------
__device__ __forceinline__ void fma2(u64& acc, u64 a, u64 b) {
    asm("fma.rn.f32x2 %0, %1, %2, %0;" : "+l"(acc) : "l"(a), "l"(b));
}
__device__ __forceinline__ float hadd2(u64 v) {
    float lo, hi;
    asm("mov.b64 {%0, %1}, %2;" : "=f"(lo), "=f"(hi) : "l"(v));
    return lo + hi;
}

// ---------------- device scratch (no allocations allowed) ----------------
__device__ __align__(16) float g_Kt[NB * CCH * MM]; // [n][c][k]
__device__ __align__(16) float g_Vt[NB * CCH * MM]; // [n][c][k]

// ---------------- kernel 1: kv = clip(gf @ W^T + b, 0, 6) ----------------
// NT GEMM (no transpose), packed f32x2 FMA, software-pipelined chunk loads.
// Tile 32 rows x 64 e, 256 threads -> grid 12x8 = 96 CTAs = ONE wave.
#define KB_E 64
#define KB_R 32
#define KB_D 64

__device__ __forceinline__ void kv_store(int row, int e, float v) {
    int n = row >> 3;
    int m = row & 7;
    if (e < CCH) g_Kt[((size_t)n * CCH + e) * MM + m] = v;
    else         g_Vt[((size_t)n * CCH + (e - CCH)) * MM + m] = v;
}

__global__ __launch_bounds__(256) void k_kv(const float* __restrict__ gf,
                                            const float* __restrict__ W,
                                            const float* __restrict__ bias) {
    __shared__ float Wc[KB_E][68];   // 17408 B
    __shared__ float Gc[KB_R][68];   //  8704 B

    int t    = threadIdx.x;
    int lane = t & 31;
    int warp = t >> 5;               // 0..7
    int eb0  = blockIdx.x * KB_E;
    int rb0  = blockIdx.y * KB_R;
    int ei   = lane & 15;            // e = eb0 + ei + 16q
    int rg   = lane >> 4;            // 0..1
    int r0   = warp * 4 + rg * 2;    // local row base (2 rows), 0..30

    int wrow = t >> 4, wf4 = t & 15; // staging coords (0..15, 0..15)

    u64 acc[4][2];
#pragma unroll
    for (int q = 0; q < 4; q++) { acc[q][0] = 0ull; acc[q][1] = 0ull; }

    // prologue: fetch chunk 0 into registers
    float4 wreg[4], greg[2];
#pragma unroll
    for (int q = 0; q < 4; q++)
        wreg[q] = *(const float4*)(W + (size_t)(eb0 + wrow + q * 16) * DD + wf4 * 4);
#pragma unroll
    for (int q = 0; q < 2; q++)
        greg[q] = *(const float4*)(gf + (size_t)(rb0 + wrow + q * 16) * DD + wf4 * 4);

    for (int kc = 0; kc < DD; kc += KB_D) {
        __syncthreads();
#pragma unroll
        for (int q = 0; q < 4; q++)
            *(float4*)(&Wc[wrow + q * 16][wf4 * 4]) = wreg[q];
#pragma unroll
        for (int q = 0; q < 2; q++)
            *(float4*)(&Gc[wrow + q * 16][wf4 * 4]) = greg[q];
        __syncthreads();
        if (kc + KB_D < DD) {
#pragma unroll
            for (int q = 0; q < 4; q++)
                wreg[q] = *(const float4*)(W + (size_t)(eb0 + wrow + q * 16) * DD + kc + KB_D + wf4 * 4);
#pragma unroll
            for (int q = 0; q < 2; q++)
                greg[q] = *(const float4*)(gf + (size_t)(rb0 + wrow + q * 16) * DD + kc + KB_D + wf4 * 4);
        }
#pragma unroll
        for (int s = 0; s < 16; s++) {
            ulonglong2 g0 = *(const ulonglong2*)(&Gc[r0][s * 4]);
            ulonglong2 g1 = *(const ulonglong2*)(&Gc[r0 + 1][s * 4]);
#pragma unroll
            for (int q = 0; q < 4; q++) {
                ulonglong2 w = *(const ulonglong2*)(&Wc[ei + 16 * q][s * 4]);
                fma2(acc[q][0], g0.x, w.x);
                fma2(acc[q][0], g0.y, w.y);
                fma2(acc[q][1], g1.x, w.x);
                fma2(acc[q][1], g1.y, w.y);
            }
        }
    }

#pragma unroll
    for (int q = 0; q < 4; q++) {
        int e = eb0 + ei + 16 * q;
        float bv = bias[e];
        float v0 = fminf(fmaxf(hadd2(acc[q][0]) + bv, 0.f), 6.f);
        float v1 = fminf(fmaxf(hadd2(acc[q][1]) + bv, 0.f), 6.f);
        kv_store(rb0 + r0,     e, v0);
        kv_store(rb0 + r0 + 1, e, v1);
    }
}

// ---------------- kernel 2: fused attention + residual (R15, measured 70us) -
// 2 pixels/thread (float2), 8 parts x 48 channels, xr register prefetch.
// Lane map: part r = lane>>2, pixel pair = lane&3 -> 4 lanes/part cover 32B.
// CTA 128 thr = 4 warps = 32 px. Grid (98, 32).
// K/V smem skew: f4 idx(c, half) = 2c + (c/48) + half ; part base = 97r
// -> 8 parts' broadcast LDS.128 land on the 8 disjoint 4-bank groups.
__global__ __launch_bounds__(128, 3) void k_attn(const float* __restrict__ x,
                                                 float* __restrict__ out) {
    __shared__ float4 Ks4[776];
    __shared__ float4 Vs4[776];

    int tid  = threadIdx.x;
    int n    = blockIdx.y;
    int lane = tid & 31;
    int warp = tid >> 5;
    int r    = lane >> 2;                        // 0..7
    int p    = blockIdx.x * 32 + warp * 8 + (lane & 3) * 2;

    const float4* Kt4 = (const float4*)g_Kt + (size_t)n * (CCH * MM / 4);
    const float4* Vt4 = (const float4*)g_Vt + (size_t)n * (CCH * MM / 4);
#pragma unroll
    for (int i = tid; i < 768; i += 128) {
        int c = i >> 1, half = i & 1;
        int dst = 2 * c + (c / 48) + half;
        Ks4[dst] = Kt4[i];
        Vs4[dst] = Vt4[i];
    }
    __syncthreads();

    const float* xp = x + ((size_t)n * CCH + r * 48) * HWP + p;
    int base = 97 * r;

    // ---- pass 1: chunked x prefetch (kept in regs) + partial scores ----
    float2 xr[48];
    float sA0=0.f,sA1=0.f,sA2=0.f,sA3=0.f,sA4=0.f,sA5=0.f,sA6=0.f,sA7=0.f;
    float sB0=0.f,sB1=0.f,sB2=0.f,sB3=0.f,sB4=0.f,sB5=0.f,sB6=0.f,sB7=0.f;
#pragma unroll
    for (int ch = 0; ch < 3; ch++) {
#pragma unroll
        for (int u = 0; u < 16; u++)
            xr[ch * 16 + u] = __ldcs((const float2*)(xp + (size_t)(ch * 16 + u) * HWP));
        asm volatile("" ::: "memory");
#pragma unroll
        for (int u = 0; u < 16; u++) {
            int j = ch * 16 + u;
            float2 xv = xr[j];
            float4 ka = Ks4[base + 2 * j];
            float4 kb = Ks4[base + 2 * j + 1];
            sA0 += xv.x * ka.x; sA1 += xv.x * ka.y; sA2 += xv.x * ka.z; sA3 += xv.x * ka.w;
            sA4 += xv.x * kb.x; sA5 += xv.x * kb.y; sA6 += xv.x * kb.z; sA7 += xv.x * kb.w;
            sB0 += xv.y * ka.x; sB1 += xv.y * ka.y; sB2 += xv.y * ka.z; sB3 += xv.y * ka.w;
            sB4 += xv.y * kb.x; sB5 += xv.y * kb.y; sB6 += xv.y * kb.z; sB7 += xv.y * kb.w;
        }
    }

    // ---- reduce across the 8 parts (butterfly over lane bits 2..4) ----
#define RED8(v) v += __shfl_xor_sync(0xffffffffu, v, 4);  \
                v += __shfl_xor_sync(0xffffffffu, v, 8);  \
                v += __shfl_xor_sync(0xffffffffu, v, 16);
    RED8(sA0) RED8(sA1) RED8(sA2) RED8(sA3)
    RED8(sA4) RED8(sA5) RED8(sA6) RED8(sA7)
    RED8(sB0) RED8(sB1) RED8(sB2) RED8(sB3)
    RED8(sB4) RED8(sB5) RED8(sB6) RED8(sB7)
#undef RED8

    // ---- softmax over 8 heads, both pixels (all lanes redundantly) ----
    float mxA = fmaxf(fmaxf(fmaxf(sA0, sA1), fmaxf(sA2, sA3)),
                      fmaxf(fmaxf(sA4, sA5), fmaxf(sA6, sA7)));
    float a0 = __expf(sA0 - mxA), a1 = __expf(sA1 - mxA);
    float a2 = __expf(sA2 - mxA), a3 = __expf(sA3 - mxA);
    float a4 = __expf(sA4 - mxA), a5 = __expf(sA5 - mxA);
    float a6 = __expf(sA6 - mxA), a7 = __expf(sA7 - mxA);
    float invA = __fdividef(1.f, a0+a1+a2+a3+a4+a5+a6+a7);
    a0*=invA; a1*=invA; a2*=invA; a3*=invA; a4*=invA; a5*=invA; a6*=invA; a7*=invA;

    float mxB = fmaxf(fmaxf(fmaxf(sB0, sB1), fmaxf(sB2, sB3)),
                      fmaxf(fmaxf(sB4, sB5), fmaxf(sB6, sB7)));
    float b0 = __expf(sB0 - mxB), b1 = __expf(sB1 - mxB);
    float b2 = __expf(sB2 - mxB), b3 = __expf(sB3 - mxB);
    float b4 = __expf(sB4 - mxB), b5 = __expf(sB5 - mxB);
    float b6 = __expf(sB6 - mxB), b7 = __expf(sB7 - mxB);
    float invB = __fdividef(1.f, b0+b1+b2+b3+b4+b5+b6+b7);
    b0*=invB; b1*=invB; b2*=invB; b3*=invB; b4*=invB; b5*=invB; b6*=invB; b7*=invB;

    // ---- pass 2: out = attn.V + x (x from registers) ----
    float* op = out + ((size_t)n * CCH + r * 48) * HWP + p;
#pragma unroll
    for (int j = 0; j < 48; j++) {
        float4 va = Vs4[base + 2 * j];
        float4 vb = Vs4[base + 2 * j + 1];
        float accA = a0 * va.x + a1 * va.y + a2 * va.z + a3 * va.w
                   + a4 * vb.x + a5 * vb.y + a6 * vb.z + a7 * vb.w;
        float accB = b0 * va.x + b1 * va.y + b2 * va.z + b3 * va.w
                   + b4 * vb.x + b5 * vb.y + b6 * vb.z + b7 * vb.w;
        float2 o;
        o.x = accA + xr[j].x;
        o.y = accB + xr[j].y;
        __stcs((float2*)(op + (size_t)j * HWP), o);
    }
}

// ---------------- launch ----------------
extern "C" void kernel_launch(void* const* d_in, const int* in_sizes, int n_in,
                              void* d_out, int out_size) {
    const float* x  = (const float*)d_in[0];
    const float* gf = (const float*)d_in[1];
    const float* W  = (const float*)d_in[2];
    const float* b  = (const float*)d_in[3];
    float* out = (float*)d_out;

    k_kv<<<dim3(EE / KB_E, 256 / KB_R), 256>>>(gf, W, b);
    k_attn<<<dim3(HWP / 32, NB), 128>>>(x, out);
}